// round 10
// baseline (speedup 1.0000x reference)
#include <cuda_runtime.h>

#define BB 64
#define TT 577
#define DD 768
#define DENS 519      // int(577*0.9)
#define NSKIP 58      // 577 - 519
#define D4 (DD/4)     // 192 float4 per row
#define RPB 8         // source rows per scatter block
#define NROWS (BB*TT) // 36928
#define NSCAT (NROWS/RPB) // 4616
#define SPLIT 8       // blocks per batch in kernel 1

// Scratch (no device allocation allowed)
__device__ float g_logits[NROWS];
__device__ int   g_rank[NROWS];
__device__ int   g_skip[BB*NSKIP];
__device__ float g_weights[BB*NSKIP];
__device__ int   g_cnt[BB];          // monotonic arrival counters (replay-safe)

// ---------------- Kernel 1: logits + (last block per batch) rank/softmax ----------------
// grid = BB*SPLIT blocks of 256; block (b, q) handles rows [q*TT/8, (q+1)*TT/8) of batch b.
__global__ void __launch_bounds__(256)
logits_rank_kernel(const float* __restrict__ x,
                   const float* __restrict__ w,
                   const float* __restrict__ bias) {
    __shared__ float s[TT];
    __shared__ float skipP[NSKIP];
    __shared__ float skipE[NSKIP];
    __shared__ int   sIsLast;

    int b = blockIdx.x >> 3;
    int q = blockIdx.x & (SPLIT - 1);
    int rs = (q * TT) / SPLIT;          // slice [rs, re) within batch
    int re = ((q + 1) * TT) / SPLIT;
    int nrows = re - rs;

    int tid = threadIdx.x;
    int warpId = tid >> 5;
    int lane   = tid & 31;

    const float4* xin = reinterpret_cast<const float4*>(x);
    const float4* w4  = reinterpret_cast<const float4*>(w);

    float4 wv[6];
    #pragma unroll
    for (int k = 0; k < 6; k++) wv[k] = __ldg(&w4[k*32 + lane]);
    float bv = __ldg(bias);

    // 2 rows per warp per iteration
    for (int p = warpId; p*2 < nrows; p += 8) {
        int row0 = b*TT + rs + 2*p;
        bool has1 = (rs + 2*p + 1) < re;    // uniform per warp

        const float4* xr0 = xin + (size_t)row0 * D4;
        float4 a0[6], a1[6];
        #pragma unroll
        for (int k = 0; k < 6; k++) a0[k] = xr0[k*32 + lane];
        if (has1) {
            const float4* xr1 = xr0 + D4;
            #pragma unroll
            for (int k = 0; k < 6; k++) a1[k] = xr1[k*32 + lane];
        }

        float acc0 = 0.f, acc1 = 0.f;
        #pragma unroll
        for (int k = 0; k < 6; k++) {
            acc0 = fmaf(a0[k].x, wv[k].x, acc0);
            acc0 = fmaf(a0[k].y, wv[k].y, acc0);
            acc0 = fmaf(a0[k].z, wv[k].z, acc0);
            acc0 = fmaf(a0[k].w, wv[k].w, acc0);
            if (has1) {
                acc1 = fmaf(a1[k].x, wv[k].x, acc1);
                acc1 = fmaf(a1[k].y, wv[k].y, acc1);
                acc1 = fmaf(a1[k].z, wv[k].z, acc1);
                acc1 = fmaf(a1[k].w, wv[k].w, acc1);
            }
        }
        #pragma unroll
        for (int off = 16; off; off >>= 1) {
            acc0 += __shfl_xor_sync(0xffffffffu, acc0, off);
            acc1 += __shfl_xor_sync(0xffffffffu, acc1, off);
        }
        if (lane == 0) {
            g_logits[row0] = acc0 + bv;
            if (has1) g_logits[row0 + 1] = acc1 + bv;
        }
    }

    // ---- last-block-does-rank handshake (1 atomic per block, no spinning) ----
    __syncthreads();
    if (tid == 0) {
        __threadfence();                              // release this slice's logits
        int old = atomicAdd(&g_cnt[b], 1);
        sIsLast = ((old & (SPLIT - 1)) == SPLIT - 1); // replay-safe (monotonic)
        if (sIsLast) __threadfence();                 // acquire: all slices visible
    }
    __syncthreads();
    if (!sIsLast) return;

    // ---- rank + skip softmax for batch b (all 8 slices now visible) ----
    for (int i = tid; i < TT; i += 256) s[i] = g_logits[b*TT + i];
    __syncthreads();

    for (int i = tid; i < TT; i += 256) {
        float my = s[i];
        int rank = 0;
        #pragma unroll 8
        for (int j = 0; j < TT; j++) {
            float v = s[j];
            rank += (v > my) || (v == my && j < i);   // stable: lower index wins
        }
        g_rank[b*TT + i] = rank;
        if (rank >= DENS) {
            int pos = (TT - 1) - rank;                // ascending skipped order
            g_skip[b*NSKIP + pos] = i;
            skipP[pos] = 1.f / (1.f + expf(-my));     // sigmoid prob
        }
    }
    __syncthreads();

    if (tid < NSKIP) {
        float m = -1e30f;
        #pragma unroll
        for (int j = 0; j < NSKIP; j++) m = fmaxf(m, skipP[j]);
        skipE[tid] = expf(skipP[tid] - m);
    }
    __syncthreads();
    if (tid < NSKIP) {
        float sum = 0.f;
        #pragma unroll
        for (int j = 0; j < NSKIP; j++) sum += skipE[j];
        g_weights[b*NSKIP + tid] = skipE[tid] / sum;
    }
}

// ---------------- Kernel 2: fused scatter + summary (no sync needed) ----------------
// Blocks [0, BB)        : MLP-8 summary for batch blockIdx.x (hidden under scatter stream)
// Blocks [BB, BB+NSCAT) : scatter RPB sequential rows, reversed traversal
__global__ void __launch_bounds__(192)
scatter_summary_kernel(const float* __restrict__ x, float* __restrict__ out) {
    const float4* xin = reinterpret_cast<const float4*>(x);
    float4* o4 = reinterpret_cast<float4*>(out);
    const size_t skipBase = (size_t)BB * DENS * D4;
    const size_t sumBase  = (size_t)BB * (DENS + NSKIP) * D4;
    int tid = threadIdx.x;              // 0..191

    if (blockIdx.x < BB) {
        // ---- summary: 8 groups of 8 front-batched loads (padded to 64, weight 0) ----
        __shared__ int   sidx[64];
        __shared__ float swgt[64];
        int b = blockIdx.x;
        if (tid < 64) {
            sidx[tid] = (tid < NSKIP) ? g_skip[b*NSKIP + tid] : 0;
            swgt[tid] = (tid < NSKIP) ? g_weights[b*NSKIP + tid] : 0.f;
        }
        __syncthreads();

        float4 acc = make_float4(0.f, 0.f, 0.f, 0.f);
        #pragma unroll
        for (int g = 0; g < 64; g += 8) {
            float4 vv[8];
            #pragma unroll
            for (int j = 0; j < 8; j++)
                vv[j] = xin[((size_t)b*TT + sidx[g+j]) * D4 + tid];
            #pragma unroll
            for (int j = 0; j < 8; j++) {
                float wgt = swgt[g+j];
                acc.x = fmaf(wgt, vv[j].x, acc.x);
                acc.y = fmaf(wgt, vv[j].y, acc.y);
                acc.z = fmaf(wgt, vv[j].z, acc.z);
                acc.w = fmaf(wgt, vv[j].w, acc.w);
            }
        }
        o4[sumBase + (size_t)b * D4 + tid] = acc;
    } else {
        // ---- scatter: rank loads first, then 8 streaming row loads, then stores ----
        int sb = (NSCAT - 1) - ((int)blockIdx.x - BB);  // reversed: freshest L2 lines first
        int base = sb * RPB;

        int rk[RPB];
        #pragma unroll
        for (int r = 0; r < RPB; r++) rk[r] = g_rank[base + r];

        float4 v[RPB];
        #pragma unroll
        for (int r = 0; r < RPB; r++)
            v[r] = __ldcs(&xin[((size_t)(base + r)) * D4 + tid]);

        #pragma unroll
        for (int r = 0; r < RPB; r++) {
            int b = (base + r) / TT;
            int rank = rk[r];
            size_t off = (rank < DENS)
                ? ((size_t)(b*DENS + rank) * D4)
                : (skipBase + (size_t)(b*NSKIP + ((TT-1) - rank)) * D4);
            __stcs(&o4[off + tid], v[r]);
        }
    }
}

extern "C" void kernel_launch(void* const* d_in, const int* in_sizes, int n_in,
                              void* d_out, int out_size) {
    const float* x    = (const float*)d_in[0];
    const float* w    = (const float*)d_in[1];
    const float* bias = (const float*)d_in[2];
    float* out = (float*)d_out;

    // 1) logits + in-kernel rank (last block per batch)
    logits_rank_kernel<<<BB * SPLIT, 256>>>(x, w, bias);
    // 2) scatter + summaries (no synchronization dependencies)
    scatter_summary_kernel<<<BB + NSCAT, 192>>>(x, out);
}

// round 11
// speedup vs baseline: 1.5437x; 1.5437x over previous
#include <cuda_runtime.h>

#define BB 64
#define TT 577
#define DD 768
#define DENS 519      // int(577*0.9)
#define NSKIP 58      // 577 - 519
#define D4 (DD/4)     // 192 float4 per row
#define RPB 8         // source rows per scatter block
#define NROWS (BB*TT) // 36928
#define NSCAT (NROWS/RPB) // 4616

// Scratch (no device allocation allowed)
__device__ float g_logits[NROWS];
__device__ int   g_rank[NROWS];
__device__ int   g_skip[BB*NSKIP];
__device__ float g_weights[BB*NSKIP];

// ---------------- Kernel 1: logits = x @ w + b  (one warp per TWO rows) ----------------
// Verified 20.8us @ 71% DRAM — do not modify.
__global__ void logits_kernel(const float* __restrict__ x,
                              const float* __restrict__ w,
                              const float* __restrict__ bias) {
    int warpsPerBlock = blockDim.x >> 5;
    int warpId = threadIdx.x >> 5;
    int lane   = threadIdx.x & 31;
    int pair = blockIdx.x * warpsPerBlock + warpId;
    int row0 = pair * 2;
    if (row0 >= NROWS) return;

    const float4* xr0 = reinterpret_cast<const float4*>(x) + (size_t)row0 * D4;
    const float4* xr1 = xr0 + D4;
    const float4* w4  = reinterpret_cast<const float4*>(w);

    float4 a0[6], a1[6], wv[6];
    #pragma unroll
    for (int k = 0; k < 6; k++) a0[k] = xr0[k*32 + lane];
    #pragma unroll
    for (int k = 0; k < 6; k++) a1[k] = xr1[k*32 + lane];
    #pragma unroll
    for (int k = 0; k < 6; k++) wv[k] = __ldg(&w4[k*32 + lane]);

    float acc0 = 0.f, acc1 = 0.f;
    #pragma unroll
    for (int k = 0; k < 6; k++) {
        acc0 = fmaf(a0[k].x, wv[k].x, acc0);
        acc0 = fmaf(a0[k].y, wv[k].y, acc0);
        acc0 = fmaf(a0[k].z, wv[k].z, acc0);
        acc0 = fmaf(a0[k].w, wv[k].w, acc0);
        acc1 = fmaf(a1[k].x, wv[k].x, acc1);
        acc1 = fmaf(a1[k].y, wv[k].y, acc1);
        acc1 = fmaf(a1[k].z, wv[k].z, acc1);
        acc1 = fmaf(a1[k].w, wv[k].w, acc1);
    }
    #pragma unroll
    for (int off = 16; off; off >>= 1) {
        acc0 += __shfl_xor_sync(0xffffffffu, acc0, off);
        acc1 += __shfl_xor_sync(0xffffffffu, acc1, off);
    }
    if (lane == 0) {
        float bv = bias[0];
        g_logits[row0]     = acc0 + bv;
        g_logits[row0 + 1] = acc1 + bv;
    }
}

// ---------------- Kernel 2: rank (stable) + skip softmax ----------------
__global__ void rank_kernel() {
    __shared__ float s[TT];
    __shared__ float skipP[NSKIP];
    __shared__ float skipE[NSKIP];

    int b = blockIdx.x;
    int i = threadIdx.x;

    if (i < TT) s[i] = g_logits[b*TT + i];
    __syncthreads();

    if (i < TT) {
        float my = s[i];
        int rank = 0;
        #pragma unroll 8
        for (int j = 0; j < TT; j++) {
            float v = s[j];
            rank += (v > my) || (v == my && j < i);   // stable: lower index wins
        }
        g_rank[b*TT + i] = rank;
        if (rank >= DENS) {
            int pos = (TT - 1) - rank;                // ascending skipped order
            g_skip[b*NSKIP + pos] = i;
            skipP[pos] = 1.f / (1.f + expf(-my));     // sigmoid prob
        }
    }
    __syncthreads();

    if (i < NSKIP) {
        float m = -1e30f;
        #pragma unroll
        for (int j = 0; j < NSKIP; j++) m = fmaxf(m, skipP[j]);
        skipE[i] = expf(skipP[i] - m);
    }
    __syncthreads();

    if (i < NSKIP) {
        float sum = 0.f;
        #pragma unroll
        for (int j = 0; j < NSKIP; j++) sum += skipE[j];
        g_weights[b*NSKIP + i] = skipE[i] / sum;
    }
}

// ---------------- Kernel 3: fused scatter + summary ----------------
// Verified 31.6us @ 5.4 TB/s — rank loads FIRST, then x loads, then stores.
// Blocks [0, BB)        : MLP-8 summary for batch blockIdx.x (hidden under scatter stream)
// Blocks [BB, BB+NSCAT) : scatter RPB sequential rows, reversed traversal
__global__ void __launch_bounds__(192)
scatter_summary_kernel(const float* __restrict__ x, float* __restrict__ out) {
    const float4* xin = reinterpret_cast<const float4*>(x);
    float4* o4 = reinterpret_cast<float4*>(out);
    const size_t skipBase = (size_t)BB * DENS * D4;
    const size_t sumBase  = (size_t)BB * (DENS + NSKIP) * D4;
    int tid = threadIdx.x;              // 0..191

    if (blockIdx.x < BB) {
        // ---- summary: 8 groups of 8 front-batched loads (padded to 64, weight 0) ----
        __shared__ int   sidx[64];
        __shared__ float swgt[64];
        int b = blockIdx.x;
        if (tid < 64) {
            sidx[tid] = (tid < NSKIP) ? g_skip[b*NSKIP + tid] : 0;
            swgt[tid] = (tid < NSKIP) ? g_weights[b*NSKIP + tid] : 0.f;
        }
        __syncthreads();

        float4 acc = make_float4(0.f, 0.f, 0.f, 0.f);
        #pragma unroll
        for (int g = 0; g < 64; g += 8) {
            float4 vv[8];
            #pragma unroll
            for (int j = 0; j < 8; j++)
                vv[j] = xin[((size_t)b*TT + sidx[g+j]) * D4 + tid];
            #pragma unroll
            for (int j = 0; j < 8; j++) {
                float wgt = swgt[g+j];
                acc.x = fmaf(wgt, vv[j].x, acc.x);
                acc.y = fmaf(wgt, vv[j].y, acc.y);
                acc.z = fmaf(wgt, vv[j].z, acc.z);
                acc.w = fmaf(wgt, vv[j].w, acc.w);
            }
        }
        o4[sumBase + (size_t)b * D4 + tid] = acc;
    } else {
        // ---- scatter: rank loads first, then 8 streaming row loads, then stores ----
        int sb = (NSCAT - 1) - ((int)blockIdx.x - BB);  // reversed: freshest L2 lines first
        int base = sb * RPB;

        int rk[RPB];
        #pragma unroll
        for (int r = 0; r < RPB; r++) rk[r] = g_rank[base + r];

        float4 v[RPB];
        #pragma unroll
        for (int r = 0; r < RPB; r++)
            v[r] = __ldcs(&xin[((size_t)(base + r)) * D4 + tid]);

        #pragma unroll
        for (int r = 0; r < RPB; r++) {
            int b = (base + r) / TT;
            int rank = rk[r];
            size_t off = (rank < DENS)
                ? ((size_t)(b*DENS + rank) * D4)
                : (skipBase + (size_t)(b*NSKIP + ((TT-1) - rank)) * D4);
            __stcs(&o4[off + tid], v[r]);
        }
    }
}

extern "C" void kernel_launch(void* const* d_in, const int* in_sizes, int n_in,
                              void* d_out, int out_size) {
    const float* x    = (const float*)d_in[0];
    const float* w    = (const float*)d_in[1];
    const float* bias = (const float*)d_in[2];
    float* out = (float*)d_out;

    // 1) logits: 2 rows/warp, 8 warps/block (verified 20.8us)
    logits_kernel<<<(NROWS/2 + 7) / 8, 256>>>(x, w, bias);
    // 2) rank + softmax (one block per batch)
    rank_kernel<<<BB, 608>>>();
    // 3) scatter + summaries (verified 31.6us)
    scatter_summary_kernel<<<BB + NSCAT, 192>>>(x, out);
}